// round 16
// baseline (speedup 1.0000x reference)
#include <cuda_runtime.h>
#include <cuda_fp16.h>
#include <math.h>
#include <stdint.h>

// ---------------------------------------------------------------------------
// DCGCN: U=I=50000 (N=100000), R=5, D=64, E=1e6/rating, B=8192. Output f32[B].
// R16: capacity-slotted edge buckets (scatter atomic IS the histogram) —
//      hist + scanA + scanC deleted. Stage0 = scatter(0) || MLP interleaved.
//      Stages 1..5 = scatter(s) || spmm0(s-1). Modes 1/2 cnt-addressed.
// ---------------------------------------------------------------------------

#define D 64
#define MAXN 100352
#define MAXR 5
#define MAXE 1048576
#define EDGE_CAP 48

__device__ __half g_bufA[(size_t)MAXR * MAXN * D];
__device__ __half g_bufB[(size_t)MAXR * MAXN * D];
__device__ float  g_sum [(size_t)MAXN * D];
__device__ int    g_cnt  [MAXR * MAXN];
__device__ int2   g_edges[(size_t)MAXR * MAXN * EDGE_CAP];
__device__ __half g_w1t[MAXR * 64 * 64];
__device__ __half g_w2t[MAXR * 64 * 64];
__device__ float  g_c1 [MAXR * 64];
__device__ float  g_b2 [MAXR * 64];
__device__ unsigned char g_need[MAXN];

__device__ __forceinline__ void red_add_v4(float* addr, float4 v) {
    asm volatile("red.global.add.v4.f32 [%0], {%1,%2,%3,%4};"
                 :: "l"(addr), "f"(v.x), "f"(v.y), "f"(v.z), "f"(v.w)
                 : "memory");
}

#define MMA16816(c0, c1, c2, c3, a0, a1, a2, a3, b0, b1) \
    asm volatile("mma.sync.aligned.m16n8k16.row.col.f32.f16.f16.f32 " \
                 "{%0,%1,%2,%3}, {%4,%5,%6,%7}, {%8,%9}, {%0,%1,%2,%3};" \
                 : "+f"(c0), "+f"(c1), "+f"(c2), "+f"(c3) \
                 : "r"(a0), "r"(a1), "r"(a2), "r"(a3), "r"(b0), "r"(b1))

// ---------------------------------------------------------------------------
// Prep (blocks 0..R-1) || mark_need (blocks >= R).
// ---------------------------------------------------------------------------
__global__ void __launch_bounds__(256) prep_need_kernel(
    const float* __restrict__ W1, const float* __restrict__ b1,
    const float* __restrict__ W2, const float* __restrict__ b2,
    const float* __restrict__ rating_emb,
    __half* __restrict__ w1t, __half* __restrict__ w2t,
    float* __restrict__ c1g, float* __restrict__ b2g,
    const int* __restrict__ users, const int* __restrict__ items,
    int U, int B, unsigned char* __restrict__ need, int R)
{
    if ((int)blockIdx.x >= R) {
        int i = (blockIdx.x - R) * 256 + threadIdx.x;
        if (i < B) {
            need[users[i]] = 1;
            need[U + items[i]] = 1;
        }
        return;
    }
    const int r = blockIdx.x;
    const int tid = threadIdx.x;
    const float* W1r = W1 + (size_t)r * 128 * 64;
    const float* W2r = W2 + (size_t)r * 64 * 64;

    for (int i = tid; i < 4096; i += 256) {
        int k = i >> 6, n = i & 63;
        w1t[(size_t)r * 4096 + n * 64 + k] = __float2half(W1r[i]);
        w2t[(size_t)r * 4096 + n * 64 + k] = __float2half(W2r[i]);
    }
    if (tid < 64) {
        float c = b1[r * 64 + tid];
        #pragma unroll 8
        for (int k = 0; k < 64; k++)
            c += rating_emb[r * 64 + k] * W1r[(64 + k) * 64 + tid];
        c1g[r * 64 + tid] = c;
        b2g[r * 64 + tid] = b2[r * 64 + tid];
    }
}

// ---------------------------------------------------------------------------
// Stage 0: scatter(rating 0) || MLP (all ratings), interleaved two-role.
// ---------------------------------------------------------------------------
#define XS_STRIDE 72
#define WS_STRIDE 72

__global__ void __launch_bounds__(256) scatter_mlp_kernel(
    const int* __restrict__ rows, const int* __restrict__ cols,
    const float* __restrict__ vals, int E, int N,
    int* __restrict__ cnt, int2* __restrict__ edges,
    int rs, int scatterBlocks,
    const float* __restrict__ user_emb, const float* __restrict__ item_emb,
    int U,
    const __half* __restrict__ w1t, const __half* __restrict__ w2t,
    const float* __restrict__ c1g, const float* __restrict__ b2g,
    __half* __restrict__ outbuf, int mlpBlocksPerR, int mlpTotal)
{
    __shared__ __half xs [128 * XS_STRIDE];
    __shared__ __half w1s[64 * WS_STRIDE];
    __shared__ __half w2s[64 * WS_STRIDE];
    __shared__ float  c1s[64];
    __shared__ float  b2s[64];

    const int bx = blockIdx.x;
    const int m2 = (scatterBlocks < mlpTotal ? scatterBlocks : mlpTotal) * 2;
    int role, idx;
    if (bx < m2) { role = bx & 1; idx = bx >> 1; }
    else if (scatterBlocks > mlpTotal) { role = 0; idx = bx - mlpTotal; }
    else { role = 1; idx = bx - scatterBlocks; }

    if (role == 0) {
        int i = idx * 256 + threadIdx.x;
        if (i < E) {
            size_t gi = (size_t)rs * E + i;
            int row = rows[gi];
            int pos = atomicAdd(&cnt[rs * N + row], 1);
            if (pos < EDGE_CAP)
                edges[((size_t)rs * N + row) * EDGE_CAP + pos] =
                    make_int2(cols[gi], __float_as_int(vals[gi]));
        }
        return;
    }

    // ---- MLP role ----
    const int r = idx / mlpBlocksPerR;
    const int row0 = (idx - r * mlpBlocksPerR) * 128;
    const int tid = threadIdx.x;
    __half* prevbuf = outbuf + (size_t)r * MAXN * D;

    const __half* w1g = w1t + (size_t)r * 4096;
    const __half* w2g = w2t + (size_t)r * 4096;
    for (int i = tid; i < 2048; i += 256) {
        int n = i >> 5, kk = (i & 31) * 2;
        *(__half2*)&w1s[n * WS_STRIDE + kk] = *(const __half2*)&w1g[n * 64 + kk];
        *(__half2*)&w2s[n * WS_STRIDE + kk] = *(const __half2*)&w2g[n * 64 + kk];
    }
    if (tid < 64) {
        c1s[tid] = c1g[r * 64 + tid];
        b2s[tid] = b2g[r * 64 + tid];
    }
    for (int i = tid; i < 128 * 16; i += 256) {
        int rr = i >> 4, c4 = i & 15;
        int row = row0 + rr;
        float4 v = make_float4(0.f, 0.f, 0.f, 0.f);
        if (row < N) {
            const float* src = (row < U) ? (user_emb + (size_t)row * 64)
                                         : (item_emb + (size_t)(row - U) * 64);
            v = ((const float4*)src)[c4];
        }
        *(__half2*)&xs[rr * XS_STRIDE + c4 * 4]     = __floats2half2_rn(v.x, v.y);
        *(__half2*)&xs[rr * XS_STRIDE + c4 * 4 + 2] = __floats2half2_rn(v.z, v.w);
    }
    __syncthreads();

    const int wid  = tid >> 5;
    const int lane = tid & 31;
    const int g    = lane >> 2;
    const int tig  = lane & 3;
    const int ar   = wid * 16;

    unsigned a[4][4];

    #pragma unroll
    for (int ks = 0; ks < 4; ks++) {
        int k0 = ks * 16;
        a[ks][0] = *(unsigned*)&xs[(ar + g)     * XS_STRIDE + k0 + tig * 2];
        a[ks][1] = *(unsigned*)&xs[(ar + g + 8) * XS_STRIDE + k0 + tig * 2];
        a[ks][2] = *(unsigned*)&xs[(ar + g)     * XS_STRIDE + k0 + tig * 2 + 8];
        a[ks][3] = *(unsigned*)&xs[(ar + g + 8) * XS_STRIDE + k0 + tig * 2 + 8];
    }

    #pragma unroll
    for (int nt = 0; nt < 8; nt++) {
        float c0 = 0.f, c1 = 0.f, c2 = 0.f, c3 = 0.f;
        #pragma unroll
        for (int ks = 0; ks < 4; ks++) {
            int k0 = ks * 16;
            unsigned b0 = *(unsigned*)&w1s[(nt * 8 + g) * WS_STRIDE + k0 + tig * 2];
            unsigned b1 = *(unsigned*)&w1s[(nt * 8 + g) * WS_STRIDE + k0 + tig * 2 + 8];
            MMA16816(c0, c1, c2, c3, a[ks][0], a[ks][1], a[ks][2], a[ks][3], b0, b1);
        }
        int col = nt * 8 + tig * 2;
        float bc0 = c1s[col], bc1 = c1s[col + 1];
        float v0 = c0 + bc0; v0 = (v0 > 0.f) ? v0 : 0.01f * v0;
        float v1 = c1 + bc1; v1 = (v1 > 0.f) ? v1 : 0.01f * v1;
        float v2 = c2 + bc0; v2 = (v2 > 0.f) ? v2 : 0.01f * v2;
        float v3 = c3 + bc1; v3 = (v3 > 0.f) ? v3 : 0.01f * v3;
        *(__half2*)&xs[(ar + g)     * XS_STRIDE + col] = __floats2half2_rn(v0, v1);
        *(__half2*)&xs[(ar + g + 8) * XS_STRIDE + col] = __floats2half2_rn(v2, v3);
    }
    __syncwarp();

    #pragma unroll
    for (int ks = 0; ks < 4; ks++) {
        int k0 = ks * 16;
        a[ks][0] = *(unsigned*)&xs[(ar + g)     * XS_STRIDE + k0 + tig * 2];
        a[ks][1] = *(unsigned*)&xs[(ar + g + 8) * XS_STRIDE + k0 + tig * 2];
        a[ks][2] = *(unsigned*)&xs[(ar + g)     * XS_STRIDE + k0 + tig * 2 + 8];
        a[ks][3] = *(unsigned*)&xs[(ar + g + 8) * XS_STRIDE + k0 + tig * 2 + 8];
    }
    __syncwarp();

    #pragma unroll
    for (int nt = 0; nt < 8; nt++) {
        float c0 = 0.f, c1 = 0.f, c2 = 0.f, c3 = 0.f;
        #pragma unroll
        for (int ks = 0; ks < 4; ks++) {
            int k0 = ks * 16;
            unsigned b0 = *(unsigned*)&w2s[(nt * 8 + g) * WS_STRIDE + k0 + tig * 2];
            unsigned b1 = *(unsigned*)&w2s[(nt * 8 + g) * WS_STRIDE + k0 + tig * 2 + 8];
            MMA16816(c0, c1, c2, c3, a[ks][0], a[ks][1], a[ks][2], a[ks][3], b0, b1);
        }
        int col = nt * 8 + tig * 2;
        float bc0 = b2s[col], bc1 = b2s[col + 1];
        *(__half2*)&xs[(ar + g)     * XS_STRIDE + col] =
            __floats2half2_rn(c0 + bc0, c1 + bc1);
        *(__half2*)&xs[(ar + g + 8) * XS_STRIDE + col] =
            __floats2half2_rn(c2 + bc0, c3 + bc1);
    }
    __syncthreads();

    for (int i = tid; i < 128 * 16; i += 256) {
        int rr = i >> 4, c = i & 15;
        uint2 v = *(uint2*)&xs[rr * XS_STRIDE + c * 4];
        *(uint2*)(prevbuf + (size_t)(row0 + rr) * 64 + c * 4) = v;
    }
}

// ---------------------------------------------------------------------------
// Gather helper for SpMM.
// ---------------------------------------------------------------------------
__device__ __forceinline__ void acc_edge(float* acc, float v, float4 raw)
{
    const __half2* h = (const __half2*)&raw;
    #pragma unroll
    for (int q = 0; q < 4; q++) {
        float2 f = __half22float2(h[q]);
        acc[2 * q]     += v * f.x;
        acc[2 * q + 1] += v * f.y;
    }
}

// ---------------------------------------------------------------------------
// Fused scatter(rating rs) || spmm-mode0(rating rp), interleaved roles.
// ---------------------------------------------------------------------------
__global__ void __launch_bounds__(256) scatter_spmm0_kernel(
    const int* __restrict__ rows, const int* __restrict__ cols,
    const float* __restrict__ vals, int E, int N,
    int* __restrict__ cnt, int2* __restrict__ edges,
    int rs, int scatterBlocks,
    const __half* __restrict__ bufA, __half* __restrict__ bufB,
    float* __restrict__ sum, const unsigned char* __restrict__ need,
    int rp, int spmmBlocks)
{
    const int bx = blockIdx.x;
    const int m2 = (scatterBlocks < spmmBlocks ? scatterBlocks : spmmBlocks) * 2;
    int role, idx;
    if (bx < m2) { role = bx & 1; idx = bx >> 1; }
    else if (scatterBlocks > spmmBlocks) { role = 0; idx = bx - spmmBlocks; }
    else { role = 1; idx = bx - scatterBlocks; }

    if (role == 0) {
        int i = idx * 256 + threadIdx.x;
        if (i < E) {
            size_t gi = (size_t)rs * E + i;
            int row = rows[gi];
            int pos = atomicAdd(&cnt[rs * N + row], 1);
            if (pos < EDGE_CAP)
                edges[((size_t)rs * N + row) * EDGE_CAP + pos] =
                    make_int2(cols[gi], __float_as_int(vals[gi]));
        }
        return;
    }

    int row  = idx * 32 + (threadIdx.x >> 3);
    int lane = threadIdx.x & 7;
    if (row >= N) return;

    const __half* prev_r = bufA + (size_t)rp * MAXN * D;

    int e = __ldg(cnt + rp * N + row);
    if (e > EDGE_CAP) e = EDGE_CAP;
    const int2* ep = edges + ((size_t)rp * N + row) * EDGE_CAP;

    float acc[8];
    #pragma unroll
    for (int d = 0; d < 8; d++) acc[d] = 0.f;

    int j = 0;
    for (; j + 3 < e; j += 4) {
        int2 e0 = __ldg(ep + j);
        int2 e1 = __ldg(ep + j + 1);
        int2 e2 = __ldg(ep + j + 2);
        int2 e3 = __ldg(ep + j + 3);
        float4 r0 = __ldg((const float4*)(prev_r + (size_t)e0.x * 64) + lane);
        float4 r1 = __ldg((const float4*)(prev_r + (size_t)e1.x * 64) + lane);
        float4 r2 = __ldg((const float4*)(prev_r + (size_t)e2.x * 64) + lane);
        float4 r3 = __ldg((const float4*)(prev_r + (size_t)e3.x * 64) + lane);
        acc_edge(acc, __int_as_float(e0.y), r0);
        acc_edge(acc, __int_as_float(e1.y), r1);
        acc_edge(acc, __int_as_float(e2.y), r2);
        acc_edge(acc, __int_as_float(e3.y), r3);
    }
    for (; j < e; j++) {
        int2 e0 = __ldg(ep + j);
        float4 r0 = __ldg((const float4*)(prev_r + (size_t)e0.x * 64) + lane);
        acc_edge(acc, __int_as_float(e0.y), r0);
    }

    const size_t goff = (size_t)rp * MAXN * D + (size_t)row * 64 + lane * 8;
    const size_t soff = (size_t)row * 64 + lane * 8;

    __half2 o0 = __floats2half2_rn(acc[0], acc[1]);
    __half2 o1 = __floats2half2_rn(acc[2], acc[3]);
    __half2 o2 = __floats2half2_rn(acc[4], acc[5]);
    __half2 o3 = __floats2half2_rn(acc[6], acc[7]);
    uint4 st = make_uint4(*(unsigned*)&o0, *(unsigned*)&o1,
                          *(unsigned*)&o2, *(unsigned*)&o3);
    *(uint4*)(bufB + goff) = st;

    if (need[row]) {
        float4 hraw = __ldg((const float4*)(bufA + goff));
        const __half2* hh = (const __half2*)&hraw;
        float hv[8];
        #pragma unroll
        for (int q = 0; q < 4; q++) {
            float2 f = __half22float2(hh[q]);
            hv[2 * q] = f.x; hv[2 * q + 1] = f.y;
        }
        red_add_v4(sum + soff, make_float4(hv[0] + acc[0], hv[1] + acc[1],
                                           hv[2] + acc[2], hv[3] + acc[3]));
        red_add_v4(sum + soff + 4, make_float4(hv[4] + acc[4], hv[5] + acc[5],
                                               hv[6] + acc[6], hv[7] + acc[7]));
    }
}

// ---------------------------------------------------------------------------
// SpMM over ALL ratings (modes 1 and 2), cnt-addressed.
// ---------------------------------------------------------------------------
__global__ void __launch_bounds__(256) spmm_all_kernel(
    const int* __restrict__ cnt, const int2* __restrict__ edges,
    const __half* __restrict__ prevbase, __half* __restrict__ nextbase,
    float* __restrict__ sum, const unsigned char* __restrict__ need,
    int N, int RN, int mode, unsigned long long mask)
{
    int gr   = blockIdx.x * 32 + (threadIdx.x >> 3);
    int lane = threadIdx.x & 7;
    if (gr >= RN) return;
    int r   = gr / N;
    int row = gr - r * N;

    if (mode == 2 && !need[row]) return;

    const __half* prev_r = prevbase + (size_t)r * MAXN * D;

    int e = __ldg(cnt + gr);
    if (e > EDGE_CAP) e = EDGE_CAP;
    const int2* ep = edges + (size_t)gr * EDGE_CAP;

    float acc[8];
    #pragma unroll
    for (int d = 0; d < 8; d++) acc[d] = 0.f;

    int j = 0;
    for (; j + 3 < e; j += 4) {
        int2 e0 = __ldg(ep + j);
        int2 e1 = __ldg(ep + j + 1);
        int2 e2 = __ldg(ep + j + 2);
        int2 e3 = __ldg(ep + j + 3);
        float4 r0 = __ldg((const float4*)(prev_r + (size_t)e0.x * 64) + lane);
        float4 r1 = __ldg((const float4*)(prev_r + (size_t)e1.x * 64) + lane);
        float4 r2 = __ldg((const float4*)(prev_r + (size_t)e2.x * 64) + lane);
        float4 r3 = __ldg((const float4*)(prev_r + (size_t)e3.x * 64) + lane);
        acc_edge(acc, __int_as_float(e0.y), r0);
        acc_edge(acc, __int_as_float(e1.y), r1);
        acc_edge(acc, __int_as_float(e2.y), r2);
        acc_edge(acc, __int_as_float(e3.y), r3);
    }
    for (; j < e; j++) {
        int2 e0 = __ldg(ep + j);
        float4 r0 = __ldg((const float4*)(prev_r + (size_t)e0.x * 64) + lane);
        acc_edge(acc, __int_as_float(e0.y), r0);
    }

    const size_t goff = (size_t)r * MAXN * D + (size_t)row * 64 + lane * 8;
    const size_t soff = (size_t)row * 64 + lane * 8;

    if (mode == 1) {
        __half2 o0 = __floats2half2_rn(acc[0], acc[1]);
        __half2 o1 = __floats2half2_rn(acc[2], acc[3]);
        __half2 o2 = __floats2half2_rn(acc[4], acc[5]);
        __half2 o3 = __floats2half2_rn(acc[6], acc[7]);
        uint4 st = make_uint4(*(unsigned*)&o0, *(unsigned*)&o1,
                              *(unsigned*)&o2, *(unsigned*)&o3);
        *(uint4*)(nextbase + goff) = st;
    } else {
        float4 praw = __ldg((const float4*)(prevbase + goff));
        const __half2* ph = (const __half2*)&praw;
        float pv[8];
        #pragma unroll
        for (int q = 0; q < 4; q++) {
            float2 f = __half22float2(ph[q]);
            pv[2 * q] = f.x; pv[2 * q + 1] = f.y;
        }
        unsigned mb = (unsigned)((mask >> (lane * 8)) & 0xFFull);
        float contrib[8];
        #pragma unroll
        for (int d = 0; d < 8; d++)
            contrib[d] = pv[d] + (((mb >> d) & 1u) ? acc[d] : pv[d]);
        red_add_v4(sum + soff, make_float4(contrib[0], contrib[1],
                                           contrib[2], contrib[3]));
        red_add_v4(sum + soff + 4, make_float4(contrib[4], contrib[5],
                                               contrib[6], contrib[7]));
    }
}

// ---------------------------------------------------------------------------
// Final: out[b] = (sum[u] . sum[U+i]) / R^2
// ---------------------------------------------------------------------------
__global__ void final_kernel(const int* __restrict__ users,
                             const int* __restrict__ items,
                             const float* __restrict__ sum,
                             int U, float invR2,
                             float* __restrict__ out, int B)
{
    int b = blockIdx.x * (blockDim.x >> 5) + (threadIdx.x >> 5);
    int lane = threadIdx.x & 31;
    if (b >= B) return;
    int u = users[b];
    int it = items[b];
    const float* pu = sum + (size_t)u * 64;
    const float* pi = sum + ((size_t)U + it) * 64;
    float acc = pu[lane] * pi[lane] + pu[lane + 32] * pi[lane + 32];
    #pragma unroll
    for (int off = 16; off; off >>= 1)
        acc += __shfl_xor_sync(0xffffffffu, acc, off);
    if (lane == 0) out[b] = acc * invR2;
}

// ---------------------------------------------------------------------------
// Host: numpy MT19937 RandomState(2).permutation(64) -> layer-2 mask bits
// ---------------------------------------------------------------------------
static unsigned long long compute_layer2_mask(int d)
{
    const int NN = 624, MM = 397;
    unsigned int key[624];
    unsigned int s = 2u;
    for (int i = 0; i < NN; i++) {
        key[i] = s;
        s = 1812433253u * (s ^ (s >> 30)) + (unsigned)i + 1u;
    }
    int pos = NN;
    auto next_u32 = [&]() -> unsigned int {
        if (pos == NN) {
            for (int i = 0; i < NN; i++) {
                unsigned int y = (key[i] & 0x80000000u) |
                                 (key[(i + 1) % NN] & 0x7fffffffu);
                unsigned int v = key[(i + MM) % NN] ^ (y >> 1);
                if (y & 1u) v ^= 0x9908b0dfu;
                key[i] = v;
            }
            pos = 0;
        }
        unsigned int y = key[pos++];
        y ^= y >> 11;
        y ^= (y << 7)  & 0x9d2c5680u;
        y ^= (y << 15) & 0xefc60000u;
        y ^= y >> 18;
        return y;
    };
    int perm[64];
    for (int i = 0; i < d; i++) perm[i] = i;
    for (int i = d - 1; i > 0; i--) {
        unsigned int m = (unsigned)i;
        m |= m >> 1; m |= m >> 2; m |= m >> 4; m |= m >> 8; m |= m >> 16;
        unsigned int j;
        do { j = next_u32() & m; } while (j > (unsigned)i);
        int t = perm[i]; perm[i] = perm[j]; perm[j] = t;
    }
    double ratio = 1.0 - log(1.0 / 2.0 + 1.0);
    int nm = (int)(ratio * d);
    unsigned long long bits = 0ull;
    for (int i = 0; i < d; i++)
        if (perm[i] >= nm) bits |= (1ull << i);
    return bits;
}

// ---------------------------------------------------------------------------
extern "C" void kernel_launch(void* const* d_in, const int* in_sizes, int n_in,
                              void* d_out, int out_size)
{
    const int*   users      = (const int*)  d_in[0];
    const int*   items      = (const int*)  d_in[1];
    const float* user_emb   = (const float*)d_in[2];
    const float* item_emb   = (const float*)d_in[3];
    const float* rating_emb = (const float*)d_in[4];
    const float* W1         = (const float*)d_in[5];
    const float* b1         = (const float*)d_in[6];
    const float* W2         = (const float*)d_in[7];
    const float* b2         = (const float*)d_in[8];
    const int*   rows       = (const int*)  d_in[9];
    const int*   cols       = (const int*)  d_in[10];
    const float* vals       = (const float*)d_in[11];

    const int B = in_sizes[0];
    const int U = in_sizes[2] / D;
    const int I = in_sizes[3] / D;
    const int N = U + I;
    const int R = in_sizes[4] / D;
    const int E = in_sizes[9] / R;

    __half *bufA, *bufB, *w1t, *w2t;
    float *sumb, *c1g, *b2g;
    int *cnt;
    int2 *edges;
    unsigned char *need;
    cudaGetSymbolAddress((void**)&bufA,  g_bufA);
    cudaGetSymbolAddress((void**)&bufB,  g_bufB);
    cudaGetSymbolAddress((void**)&sumb,  g_sum);
    cudaGetSymbolAddress((void**)&cnt,   g_cnt);
    cudaGetSymbolAddress((void**)&edges, g_edges);
    cudaGetSymbolAddress((void**)&w1t,   g_w1t);
    cudaGetSymbolAddress((void**)&w2t,   g_w2t);
    cudaGetSymbolAddress((void**)&c1g,   g_c1);
    cudaGetSymbolAddress((void**)&b2g,   g_b2);
    cudaGetSymbolAddress((void**)&need,  g_need);

    const unsigned long long mask2 = compute_layer2_mask(D);

    const int totRN = R * N;
    const int scatBlocksPerR = (E + 255) / 256;
    const int spmmBlocksPerR = (N + 31) / 32;
    const int mlpBlocksPerR = (N + 127) / 128;
    const int mlpTotal = R * mlpBlocksPerR;

    // ---- memsets + prep||need ----
    cudaMemsetAsync(cnt, 0, totRN * sizeof(int), 0);
    cudaMemsetAsync(sumb, 0, (size_t)N * D * sizeof(float), 0);
    cudaMemsetAsync(need, 0, N, 0);
    prep_need_kernel<<<R + (B + 255) / 256, 256>>>(
        W1, b1, W2, b2, rating_emb, w1t, w2t, c1g, b2g,
        users, items, U, B, need, R);

    // ---- stage 0: scatter(0) || MLP ----
    scatter_mlp_kernel<<<scatBlocksPerR + mlpTotal, 256>>>(
        rows, cols, vals, E, N, cnt, edges, 0, scatBlocksPerR,
        user_emb, item_emb, U, w1t, w2t, c1g, b2g, bufA,
        mlpBlocksPerR, mlpTotal);

    // ---- stages 1..R: scatter(s) || spmm0(s-1) ----
    for (int s = 1; s <= R; s++) {
        int rs = (s < R) ? s : -1;
        int rp = s - 1;
        int sb = (rs >= 0) ? scatBlocksPerR : 0;
        scatter_spmm0_kernel<<<sb + spmmBlocksPerR, 256>>>(
            rows, cols, vals, E, N, cnt, edges, rs, sb,
            bufA, bufB, sumb, need, rp, spmmBlocksPerR);
    }

    // ---- modes 1 and 2 over all ratings ----
    const int spmm_grid = (totRN + 31) / 32;
    spmm_all_kernel<<<spmm_grid, 256>>>(cnt, edges, bufB, bufA, sumb, need,
                                        N, totRN, 1, 0ull);
    spmm_all_kernel<<<spmm_grid, 256>>>(cnt, edges, bufA, bufB, sumb, need,
                                        N, totRN, 2, mask2);

    const float invR2 = 1.0f / (float)(R * R);
    const int fin_grid = (B + 7) / 8;
    final_kernel<<<fin_grid, 256>>>(users, items, sumb, U, invR2,
                                    (float*)d_out, B);
}

// round 17
// speedup vs baseline: 1.0613x; 1.0613x over previous
#include <cuda_runtime.h>
#include <cuda_fp16.h>
#include <math.h>
#include <stdint.h>

// ---------------------------------------------------------------------------
// DCGCN: U=I=50000 (N=100000), R=5, D=64, E=1e6/rating, B=8192. Output f32[B].
// R17: R15 (CSR, best known) + hist role at 4 edges/thread (int4) with
//      balanced hist||MLP interleave. Slotted layout reverted (R16 lesson:
//      edge-read density beats deleting scans on an LTS-capped kernel).
// ---------------------------------------------------------------------------

#define D 64
#define MAXN 100352
#define MAXR 5
#define MAXE 1048576

__device__ __half g_bufA[(size_t)MAXR * MAXN * D];
__device__ __half g_bufB[(size_t)MAXR * MAXN * D];
__device__ float  g_sum [(size_t)MAXN * D];
__device__ int    g_deg  [MAXR * MAXN];
__device__ int    g_start[MAXR * MAXN + 1];
__device__ int    g_bsum [1024];
__device__ int2   g_edges[(size_t)MAXR * MAXE];
__device__ __half g_w1t[MAXR * 64 * 64];
__device__ __half g_w2t[MAXR * 64 * 64];
__device__ float  g_c1 [MAXR * 64];
__device__ float  g_b2 [MAXR * 64];
__device__ unsigned char g_need[MAXN];

__device__ __forceinline__ void red_add_v4(float* addr, float4 v) {
    asm volatile("red.global.add.v4.f32 [%0], {%1,%2,%3,%4};"
                 :: "l"(addr), "f"(v.x), "f"(v.y), "f"(v.z), "f"(v.w)
                 : "memory");
}

#define MMA16816(c0, c1, c2, c3, a0, a1, a2, a3, b0, b1) \
    asm volatile("mma.sync.aligned.m16n8k16.row.col.f32.f16.f16.f32 " \
                 "{%0,%1,%2,%3}, {%4,%5,%6,%7}, {%8,%9}, {%0,%1,%2,%3};" \
                 : "+f"(c0), "+f"(c1), "+f"(c2), "+f"(c3) \
                 : "r"(a0), "r"(a1), "r"(a2), "r"(a3), "r"(b0), "r"(b1))

// ---------------------------------------------------------------------------
// Prep (blocks 0..R-1) || mark_need (blocks >= R). Both smem-free.
// ---------------------------------------------------------------------------
__global__ void __launch_bounds__(256) prep_need_kernel(
    const float* __restrict__ W1, const float* __restrict__ b1,
    const float* __restrict__ W2, const float* __restrict__ b2,
    const float* __restrict__ rating_emb,
    __half* __restrict__ w1t, __half* __restrict__ w2t,
    float* __restrict__ c1g, float* __restrict__ b2g,
    const int* __restrict__ users, const int* __restrict__ items,
    int U, int B, unsigned char* __restrict__ need, int R)
{
    if ((int)blockIdx.x >= R) {
        int i = (blockIdx.x - R) * 256 + threadIdx.x;
        if (i < B) {
            need[users[i]] = 1;
            need[U + items[i]] = 1;
        }
        return;
    }
    const int r = blockIdx.x;
    const int tid = threadIdx.x;
    const float* W1r = W1 + (size_t)r * 128 * 64;
    const float* W2r = W2 + (size_t)r * 64 * 64;

    for (int i = tid; i < 4096; i += 256) {
        int k = i >> 6, n = i & 63;
        w1t[(size_t)r * 4096 + n * 64 + k] = __float2half(W1r[i]);
        w2t[(size_t)r * 4096 + n * 64 + k] = __float2half(W2r[i]);
    }
    if (tid < 64) {
        float c = b1[r * 64 + tid];
        #pragma unroll 8
        for (int k = 0; k < 64; k++)
            c += rating_emb[r * 64 + k] * W1r[(64 + k) * 64 + tid];
        c1g[r * 64 + tid] = c;
        b2g[r * 64 + tid] = b2[r * 64 + tid];
    }
}

// ---------------------------------------------------------------------------
// Fused hist || MLP, balanced alternating interleave.
// hist role: 4 edges per thread (int4 load), 1024 edges per block.
// ---------------------------------------------------------------------------
#define XS_STRIDE 72
#define WS_STRIDE 72

__global__ void __launch_bounds__(256) hist_mlp_kernel(
    const int* __restrict__ rows, int E, int N,
    int* __restrict__ deg, int totE, int histBlocks,
    const float* __restrict__ user_emb, const float* __restrict__ item_emb,
    int U,
    const __half* __restrict__ w1t, const __half* __restrict__ w2t,
    const float* __restrict__ c1g, const float* __restrict__ b2g,
    __half* __restrict__ outbuf, int mlpBlocksPerR, int mlpTotal)
{
    __shared__ __half xs [128 * XS_STRIDE];
    __shared__ __half w1s[64 * WS_STRIDE];
    __shared__ __half w2s[64 * WS_STRIDE];
    __shared__ float  c1s[64];
    __shared__ float  b2s[64];

    const int bx = blockIdx.x;
    const int m2 = (histBlocks < mlpTotal ? histBlocks : mlpTotal) * 2;
    int role, idx;
    if (bx < m2) { role = bx & 1; idx = bx >> 1; }
    else if (histBlocks > mlpTotal) { role = 0; idx = bx - mlpTotal; }
    else { role = 1; idx = bx - histBlocks; }

    if (role == 0) {
        int i4 = (idx * 256 + threadIdx.x) * 4;
        if (i4 + 3 < totE) {
            int4 rr = *(const int4*)(rows + i4);
            int r0 = i4 / E;            // E % 4 == 0 for this dataset, but
            int r3 = (i4 + 3) / E;      // compute both ends to stay safe
            if (r0 == r3) {
                int base = r0 * N;
                atomicAdd(&deg[base + rr.x], 1);
                atomicAdd(&deg[base + rr.y], 1);
                atomicAdd(&deg[base + rr.z], 1);
                atomicAdd(&deg[base + rr.w], 1);
            } else {
                atomicAdd(&deg[((i4    ) / E) * N + rr.x], 1);
                atomicAdd(&deg[((i4 + 1) / E) * N + rr.y], 1);
                atomicAdd(&deg[((i4 + 2) / E) * N + rr.z], 1);
                atomicAdd(&deg[((i4 + 3) / E) * N + rr.w], 1);
            }
        } else {
            for (int k = 0; k < 4; k++) {
                int i = i4 + k;
                if (i < totE)
                    atomicAdd(&deg[(i / E) * N + rows[i]], 1);
            }
        }
        return;
    }

    // ---- MLP role ----
    const int r = idx / mlpBlocksPerR;
    const int row0 = (idx - r * mlpBlocksPerR) * 128;
    const int tid = threadIdx.x;
    __half* prevbuf = outbuf + (size_t)r * MAXN * D;

    const __half* w1g = w1t + (size_t)r * 4096;
    const __half* w2g = w2t + (size_t)r * 4096;
    for (int i = tid; i < 2048; i += 256) {
        int n = i >> 5, kk = (i & 31) * 2;
        *(__half2*)&w1s[n * WS_STRIDE + kk] = *(const __half2*)&w1g[n * 64 + kk];
        *(__half2*)&w2s[n * WS_STRIDE + kk] = *(const __half2*)&w2g[n * 64 + kk];
    }
    if (tid < 64) {
        c1s[tid] = c1g[r * 64 + tid];
        b2s[tid] = b2g[r * 64 + tid];
    }
    for (int i = tid; i < 128 * 16; i += 256) {
        int rr = i >> 4, c4 = i & 15;
        int row = row0 + rr;
        float4 v = make_float4(0.f, 0.f, 0.f, 0.f);
        if (row < N) {
            const float* src = (row < U) ? (user_emb + (size_t)row * 64)
                                         : (item_emb + (size_t)(row - U) * 64);
            v = ((const float4*)src)[c4];
        }
        *(__half2*)&xs[rr * XS_STRIDE + c4 * 4]     = __floats2half2_rn(v.x, v.y);
        *(__half2*)&xs[rr * XS_STRIDE + c4 * 4 + 2] = __floats2half2_rn(v.z, v.w);
    }
    __syncthreads();

    const int wid  = tid >> 5;
    const int lane = tid & 31;
    const int g    = lane >> 2;
    const int tig  = lane & 3;
    const int ar   = wid * 16;

    unsigned a[4][4];

    #pragma unroll
    for (int ks = 0; ks < 4; ks++) {
        int k0 = ks * 16;
        a[ks][0] = *(unsigned*)&xs[(ar + g)     * XS_STRIDE + k0 + tig * 2];
        a[ks][1] = *(unsigned*)&xs[(ar + g + 8) * XS_STRIDE + k0 + tig * 2];
        a[ks][2] = *(unsigned*)&xs[(ar + g)     * XS_STRIDE + k0 + tig * 2 + 8];
        a[ks][3] = *(unsigned*)&xs[(ar + g + 8) * XS_STRIDE + k0 + tig * 2 + 8];
    }

    #pragma unroll
    for (int nt = 0; nt < 8; nt++) {
        float c0 = 0.f, c1 = 0.f, c2 = 0.f, c3 = 0.f;
        #pragma unroll
        for (int ks = 0; ks < 4; ks++) {
            int k0 = ks * 16;
            unsigned b0 = *(unsigned*)&w1s[(nt * 8 + g) * WS_STRIDE + k0 + tig * 2];
            unsigned b1 = *(unsigned*)&w1s[(nt * 8 + g) * WS_STRIDE + k0 + tig * 2 + 8];
            MMA16816(c0, c1, c2, c3, a[ks][0], a[ks][1], a[ks][2], a[ks][3], b0, b1);
        }
        int col = nt * 8 + tig * 2;
        float bc0 = c1s[col], bc1 = c1s[col + 1];
        float v0 = c0 + bc0; v0 = (v0 > 0.f) ? v0 : 0.01f * v0;
        float v1 = c1 + bc1; v1 = (v1 > 0.f) ? v1 : 0.01f * v1;
        float v2 = c2 + bc0; v2 = (v2 > 0.f) ? v2 : 0.01f * v2;
        float v3 = c3 + bc1; v3 = (v3 > 0.f) ? v3 : 0.01f * v3;
        *(__half2*)&xs[(ar + g)     * XS_STRIDE + col] = __floats2half2_rn(v0, v1);
        *(__half2*)&xs[(ar + g + 8) * XS_STRIDE + col] = __floats2half2_rn(v2, v3);
    }
    __syncwarp();

    #pragma unroll
    for (int ks = 0; ks < 4; ks++) {
        int k0 = ks * 16;
        a[ks][0] = *(unsigned*)&xs[(ar + g)     * XS_STRIDE + k0 + tig * 2];
        a[ks][1] = *(unsigned*)&xs[(ar + g + 8) * XS_STRIDE + k0 + tig * 2];
        a[ks][2] = *(unsigned*)&xs[(ar + g)     * XS_STRIDE + k0 + tig * 2 + 8];
        a[ks][3] = *(unsigned*)&xs[(ar + g + 8) * XS_STRIDE + k0 + tig * 2 + 8];
    }
    __syncwarp();

    #pragma unroll
    for (int nt = 0; nt < 8; nt++) {
        float c0 = 0.f, c1 = 0.f, c2 = 0.f, c3 = 0.f;
        #pragma unroll
        for (int ks = 0; ks < 4; ks++) {
            int k0 = ks * 16;
            unsigned b0 = *(unsigned*)&w2s[(nt * 8 + g) * WS_STRIDE + k0 + tig * 2];
            unsigned b1 = *(unsigned*)&w2s[(nt * 8 + g) * WS_STRIDE + k0 + tig * 2 + 8];
            MMA16816(c0, c1, c2, c3, a[ks][0], a[ks][1], a[ks][2], a[ks][3], b0, b1);
        }
        int col = nt * 8 + tig * 2;
        float bc0 = b2s[col], bc1 = b2s[col + 1];
        *(__half2*)&xs[(ar + g)     * XS_STRIDE + col] =
            __floats2half2_rn(c0 + bc0, c1 + bc1);
        *(__half2*)&xs[(ar + g + 8) * XS_STRIDE + col] =
            __floats2half2_rn(c2 + bc0, c3 + bc1);
    }
    __syncthreads();

    for (int i = tid; i < 128 * 16; i += 256) {
        int rr = i >> 4, c = i & 15;
        uint2 v = *(uint2*)&xs[rr * XS_STRIDE + c * 4];
        *(uint2*)(prevbuf + (size_t)(row0 + rr) * 64 + c * 4) = v;
    }
}

// ---------------------------------------------------------------------------
// Warp-shuffle scans.
// ---------------------------------------------------------------------------
__global__ void __launch_bounds__(1024) scanA_kernel(
    const int* __restrict__ deg, int tot,
    int* __restrict__ out, int* __restrict__ bsum)
{
    __shared__ int wsum[32];
    int i = blockIdx.x * 1024 + threadIdx.x;
    int lane = threadIdx.x & 31, wid = threadIdx.x >> 5;
    int v = (i < tot) ? deg[i] : 0;
    int x = v;
    #pragma unroll
    for (int o = 1; o < 32; o <<= 1) {
        int t = __shfl_up_sync(0xffffffffu, x, o);
        if (lane >= o) x += t;
    }
    if (lane == 31) wsum[wid] = x;
    __syncthreads();
    if (wid == 0) {
        int w = wsum[lane];
        #pragma unroll
        for (int o = 1; o < 32; o <<= 1) {
            int t = __shfl_up_sync(0xffffffffu, w, o);
            if (lane >= o) w += t;
        }
        wsum[lane] = w;
    }
    __syncthreads();
    int off = (wid > 0) ? wsum[wid - 1] : 0;
    int incl = x + off;
    if (i < tot) out[i] = incl - v;
    if (threadIdx.x == 1023) bsum[blockIdx.x] = incl;
}

__global__ void __launch_bounds__(1024) scanC_kernel(
    int* __restrict__ start, int* __restrict__ cursor,
    const int* __restrict__ bsum, int nblk, int tot, int totE)
{
    __shared__ int wsum[32];
    __shared__ int sm[1024];
    int lane = threadIdx.x & 31, wid = threadIdx.x >> 5;
    int v = (threadIdx.x < nblk) ? bsum[threadIdx.x] : 0;
    int x = v;
    #pragma unroll
    for (int o = 1; o < 32; o <<= 1) {
        int t = __shfl_up_sync(0xffffffffu, x, o);
        if (lane >= o) x += t;
    }
    if (lane == 31) wsum[wid] = x;
    __syncthreads();
    if (wid == 0) {
        int w = wsum[lane];
        #pragma unroll
        for (int o = 1; o < 32; o <<= 1) {
            int t = __shfl_up_sync(0xffffffffu, w, o);
            if (lane >= o) w += t;
        }
        wsum[lane] = w;
    }
    __syncthreads();
    int woff = (wid > 0) ? wsum[wid - 1] : 0;
    sm[threadIdx.x] = x + woff;
    __syncthreads();
    int off = (blockIdx.x == 0) ? 0 : sm[blockIdx.x - 1];
    int i = blockIdx.x * 1024 + threadIdx.x;
    if (i < tot) {
        int s = start[i] + off;
        start[i]  = s;
        cursor[i] = s;
    }
    if (i == 0) start[tot] = totE;
}

// ---------------------------------------------------------------------------
// Gather helper for SpMM.
// ---------------------------------------------------------------------------
__device__ __forceinline__ void acc_edge(float* acc, float v, float4 raw)
{
    const __half2* h = (const __half2*)&raw;
    #pragma unroll
    for (int q = 0; q < 4; q++) {
        float2 f = __half22float2(h[q]);
        acc[2 * q]     += v * f.x;
        acc[2 * q + 1] += v * f.y;
    }
}

// ---------------------------------------------------------------------------
// Fused scatter(rating rs) || spmm-mode0(rating rp), interleaved roles.
// ---------------------------------------------------------------------------
__global__ void __launch_bounds__(256) scatter_spmm0_kernel(
    const int* __restrict__ rows, const int* __restrict__ cols,
    const float* __restrict__ vals, int E, int N,
    int* __restrict__ cursor, int2* __restrict__ edges,
    int rs, int scatterBlocks,
    const int* __restrict__ start,
    const __half* __restrict__ bufA, __half* __restrict__ bufB,
    float* __restrict__ sum, const unsigned char* __restrict__ need,
    int rp, int spmmBlocks)
{
    const int bx = blockIdx.x;
    const int m2 = (scatterBlocks < spmmBlocks ? scatterBlocks : spmmBlocks) * 2;
    int role, idx;
    if (bx < m2) { role = bx & 1; idx = bx >> 1; }
    else if (scatterBlocks > spmmBlocks) { role = 0; idx = bx - spmmBlocks; }
    else { role = 1; idx = bx - scatterBlocks; }

    if (role == 0) {
        int i = idx * 256 + threadIdx.x;
        if (i < E) {
            size_t gi = (size_t)rs * E + i;
            int pos = atomicAdd(&cursor[rs * N + rows[gi]], 1);
            edges[pos] = make_int2(cols[gi], __float_as_int(vals[gi]));
        }
        return;
    }

    int row  = idx * 32 + (threadIdx.x >> 3);
    int lane = threadIdx.x & 7;
    if (row >= N) return;
    int gr = rp * N + row;

    const __half* prev_r = bufA + (size_t)rp * MAXN * D;

    int s = __ldg(start + gr);
    int e = __ldg(start + gr + 1);

    float acc[8];
    #pragma unroll
    for (int d = 0; d < 8; d++) acc[d] = 0.f;

    int j = s;
    for (; j + 3 < e; j += 4) {
        int2 e0 = __ldg(edges + j);
        int2 e1 = __ldg(edges + j + 1);
        int2 e2 = __ldg(edges + j + 2);
        int2 e3 = __ldg(edges + j + 3);
        float4 r0 = __ldg((const float4*)(prev_r + (size_t)e0.x * 64) + lane);
        float4 r1 = __ldg((const float4*)(prev_r + (size_t)e1.x * 64) + lane);
        float4 r2 = __ldg((const float4*)(prev_r + (size_t)e2.x * 64) + lane);
        float4 r3 = __ldg((const float4*)(prev_r + (size_t)e3.x * 64) + lane);
        acc_edge(acc, __int_as_float(e0.y), r0);
        acc_edge(acc, __int_as_float(e1.y), r1);
        acc_edge(acc, __int_as_float(e2.y), r2);
        acc_edge(acc, __int_as_float(e3.y), r3);
    }
    for (; j < e; j++) {
        int2 e0 = __ldg(edges + j);
        float4 r0 = __ldg((const float4*)(prev_r + (size_t)e0.x * 64) + lane);
        acc_edge(acc, __int_as_float(e0.y), r0);
    }

    const size_t goff = (size_t)rp * MAXN * D + (size_t)row * 64 + lane * 8;
    const size_t soff = (size_t)row * 64 + lane * 8;

    __half2 o0 = __floats2half2_rn(acc[0], acc[1]);
    __half2 o1 = __floats2half2_rn(acc[2], acc[3]);
    __half2 o2 = __floats2half2_rn(acc[4], acc[5]);
    __half2 o3 = __floats2half2_rn(acc[6], acc[7]);
    uint4 st = make_uint4(*(unsigned*)&o0, *(unsigned*)&o1,
                          *(unsigned*)&o2, *(unsigned*)&o3);
    *(uint4*)(bufB + goff) = st;

    if (need[row]) {
        float4 hraw = __ldg((const float4*)(bufA + goff));
        const __half2* hh = (const __half2*)&hraw;
        float hv[8];
        #pragma unroll
        for (int q = 0; q < 4; q++) {
            float2 f = __half22float2(hh[q]);
            hv[2 * q] = f.x; hv[2 * q + 1] = f.y;
        }
        red_add_v4(sum + soff, make_float4(hv[0] + acc[0], hv[1] + acc[1],
                                           hv[2] + acc[2], hv[3] + acc[3]));
        red_add_v4(sum + soff + 4, make_float4(hv[4] + acc[4], hv[5] + acc[5],
                                               hv[6] + acc[6], hv[7] + acc[7]));
    }
}

// ---------------------------------------------------------------------------
// CSR SpMM over ALL ratings (modes 1 and 2).
// ---------------------------------------------------------------------------
__global__ void __launch_bounds__(256) spmm_all_kernel(
    const int* __restrict__ start, const int2* __restrict__ edges,
    const __half* __restrict__ prevbase, __half* __restrict__ nextbase,
    float* __restrict__ sum, const unsigned char* __restrict__ need,
    int N, int RN, int mode, unsigned long long mask)
{
    int gr   = blockIdx.x * 32 + (threadIdx.x >> 3);
    int lane = threadIdx.x & 7;
    if (gr >= RN) return;
    int r   = gr / N;
    int row = gr - r * N;

    if (mode == 2 && !need[row]) return;

    const __half* prev_r = prevbase + (size_t)r * MAXN * D;

    int s = __ldg(start + gr);
    int e = __ldg(start + gr + 1);

    float acc[8];
    #pragma unroll
    for (int d = 0; d < 8; d++) acc[d] = 0.f;

    int j = s;
    for (; j + 3 < e; j += 4) {
        int2 e0 = __ldg(edges + j);
        int2 e1 = __ldg(edges + j + 1);
        int2 e2 = __ldg(edges + j + 2);
        int2 e3 = __ldg(edges + j + 3);
        float4 r0 = __ldg((const float4*)(prev_r + (size_t)e0.x * 64) + lane);
        float4 r1 = __ldg((const float4*)(prev_r + (size_t)e1.x * 64) + lane);
        float4 r2 = __ldg((const float4*)(prev_r + (size_t)e2.x * 64) + lane);
        float4 r3 = __ldg((const float4*)(prev_r + (size_t)e3.x * 64) + lane);
        acc_edge(acc, __int_as_float(e0.y), r0);
        acc_edge(acc, __int_as_float(e1.y), r1);
        acc_edge(acc, __int_as_float(e2.y), r2);
        acc_edge(acc, __int_as_float(e3.y), r3);
    }
    for (; j < e; j++) {
        int2 e0 = __ldg(edges + j);
        float4 r0 = __ldg((const float4*)(prev_r + (size_t)e0.x * 64) + lane);
        acc_edge(acc, __int_as_float(e0.y), r0);
    }

    const size_t goff = (size_t)r * MAXN * D + (size_t)row * 64 + lane * 8;
    const size_t soff = (size_t)row * 64 + lane * 8;

    if (mode == 1) {
        __half2 o0 = __floats2half2_rn(acc[0], acc[1]);
        __half2 o1 = __floats2half2_rn(acc[2], acc[3]);
        __half2 o2 = __floats2half2_rn(acc[4], acc[5]);
        __half2 o3 = __floats2half2_rn(acc[6], acc[7]);
        uint4 st = make_uint4(*(unsigned*)&o0, *(unsigned*)&o1,
                              *(unsigned*)&o2, *(unsigned*)&o3);
        *(uint4*)(nextbase + goff) = st;
    } else {
        float4 praw = __ldg((const float4*)(prevbase + goff));
        const __half2* ph = (const __half2*)&praw;
        float pv[8];
        #pragma unroll
        for (int q = 0; q < 4; q++) {
            float2 f = __half22float2(ph[q]);
            pv[2 * q] = f.x; pv[2 * q + 1] = f.y;
        }
        unsigned mb = (unsigned)((mask >> (lane * 8)) & 0xFFull);
        float contrib[8];
        #pragma unroll
        for (int d = 0; d < 8; d++)
            contrib[d] = pv[d] + (((mb >> d) & 1u) ? acc[d] : pv[d]);
        red_add_v4(sum + soff, make_float4(contrib[0], contrib[1],
                                           contrib[2], contrib[3]));
        red_add_v4(sum + soff + 4, make_float4(contrib[4], contrib[5],
                                               contrib[6], contrib[7]));
    }
}

// ---------------------------------------------------------------------------
// Final: out[b] = (sum[u] . sum[U+i]) / R^2
// ---------------------------------------------------------------------------
__global__ void final_kernel(const int* __restrict__ users,
                             const int* __restrict__ items,
                             const float* __restrict__ sum,
                             int U, float invR2,
                             float* __restrict__ out, int B)
{
    int b = blockIdx.x * (blockDim.x >> 5) + (threadIdx.x >> 5);
    int lane = threadIdx.x & 31;
    if (b >= B) return;
    int u = users[b];
    int it = items[b];
    const float* pu = sum + (size_t)u * 64;
    const float* pi = sum + ((size_t)U + it) * 64;
    float acc = pu[lane] * pi[lane] + pu[lane + 32] * pi[lane + 32];
    #pragma unroll
    for (int off = 16; off; off >>= 1)
        acc += __shfl_xor_sync(0xffffffffu, acc, off);
    if (lane == 0) out[b] = acc * invR2;
}

// ---------------------------------------------------------------------------
// Host: numpy MT19937 RandomState(2).permutation(64) -> layer-2 mask bits
// ---------------------------------------------------------------------------
static unsigned long long compute_layer2_mask(int d)
{
    const int NN = 624, MM = 397;
    unsigned int key[624];
    unsigned int s = 2u;
    for (int i = 0; i < NN; i++) {
        key[i] = s;
        s = 1812433253u * (s ^ (s >> 30)) + (unsigned)i + 1u;
    }
    int pos = NN;
    auto next_u32 = [&]() -> unsigned int {
        if (pos == NN) {
            for (int i = 0; i < NN; i++) {
                unsigned int y = (key[i] & 0x80000000u) |
                                 (key[(i + 1) % NN] & 0x7fffffffu);
                unsigned int v = key[(i + MM) % NN] ^ (y >> 1);
                if (y & 1u) v ^= 0x9908b0dfu;
                key[i] = v;
            }
            pos = 0;
        }
        unsigned int y = key[pos++];
        y ^= y >> 11;
        y ^= (y << 7)  & 0x9d2c5680u;
        y ^= (y << 15) & 0xefc60000u;
        y ^= y >> 18;
        return y;
    };
    int perm[64];
    for (int i = 0; i < d; i++) perm[i] = i;
    for (int i = d - 1; i > 0; i--) {
        unsigned int m = (unsigned)i;
        m |= m >> 1; m |= m >> 2; m |= m >> 4; m |= m >> 8; m |= m >> 16;
        unsigned int j;
        do { j = next_u32() & m; } while (j > (unsigned)i);
        int t = perm[i]; perm[i] = perm[j]; perm[j] = t;
    }
    double ratio = 1.0 - log(1.0 / 2.0 + 1.0);
    int nm = (int)(ratio * d);
    unsigned long long bits = 0ull;
    for (int i = 0; i < d; i++)
        if (perm[i] >= nm) bits |= (1ull << i);
    return bits;
}

// ---------------------------------------------------------------------------
extern "C" void kernel_launch(void* const* d_in, const int* in_sizes, int n_in,
                              void* d_out, int out_size)
{
    const int*   users      = (const int*)  d_in[0];
    const int*   items      = (const int*)  d_in[1];
    const float* user_emb   = (const float*)d_in[2];
    const float* item_emb   = (const float*)d_in[3];
    const float* rating_emb = (const float*)d_in[4];
    const float* W1         = (const float*)d_in[5];
    const float* b1         = (const float*)d_in[6];
    const float* W2         = (const float*)d_in[7];
    const float* b2         = (const float*)d_in[8];
    const int*   rows       = (const int*)  d_in[9];
    const int*   cols       = (const int*)  d_in[10];
    const float* vals       = (const float*)d_in[11];

    const int B = in_sizes[0];
    const int U = in_sizes[2] / D;
    const int I = in_sizes[3] / D;
    const int N = U + I;
    const int R = in_sizes[4] / D;
    const int E = in_sizes[9] / R;

    __half *bufA, *bufB, *w1t, *w2t;
    float *sumb, *c1g, *b2g;
    int *deg, *startp, *bsum;
    int2 *edges;
    unsigned char *need;
    cudaGetSymbolAddress((void**)&bufA,  g_bufA);
    cudaGetSymbolAddress((void**)&bufB,  g_bufB);
    cudaGetSymbolAddress((void**)&sumb,  g_sum);
    cudaGetSymbolAddress((void**)&deg,   g_deg);
    cudaGetSymbolAddress((void**)&startp,g_start);
    cudaGetSymbolAddress((void**)&bsum,  g_bsum);
    cudaGetSymbolAddress((void**)&edges, g_edges);
    cudaGetSymbolAddress((void**)&w1t,   g_w1t);
    cudaGetSymbolAddress((void**)&w2t,   g_w2t);
    cudaGetSymbolAddress((void**)&c1g,   g_c1);
    cudaGetSymbolAddress((void**)&b2g,   g_b2);
    cudaGetSymbolAddress((void**)&need,  g_need);

    const unsigned long long mask2 = compute_layer2_mask(D);

    const int totRN = R * N;
    const int totRE = R * E;
    const int nblk  = (totRN + 1023) / 1024;
    const int histBlocks = (totRE + 1023) / 1024;   // 4 edges/thread
    const int scatBlocksPerR = (E + 255) / 256;
    const int spmmBlocksPerR = (N + 31) / 32;
    const int mlpBlocksPerR = (N + 127) / 128;
    const int mlpTotal = R * mlpBlocksPerR;

    // ---- memsets + prep||need ----
    cudaMemsetAsync(deg, 0, totRN * sizeof(int), 0);
    cudaMemsetAsync(sumb, 0, (size_t)N * D * sizeof(float), 0);
    cudaMemsetAsync(need, 0, N, 0);
    prep_need_kernel<<<R + (B + 255) / 256, 256>>>(
        W1, b1, W2, b2, rating_emb, w1t, w2t, c1g, b2g,
        users, items, U, B, need, R);

    // ---- interleaved hist || MLP ----
    hist_mlp_kernel<<<histBlocks + mlpTotal, 256>>>(
        rows, E, N, deg, totRE, histBlocks,
        user_emb, item_emb, U, w1t, w2t, c1g, b2g, bufA,
        mlpBlocksPerR, mlpTotal);

    // ---- scans ----
    scanA_kernel<<<nblk, 1024>>>(deg, totRN, startp, bsum);
    scanC_kernel<<<nblk, 1024>>>(startp, deg, bsum, nblk, totRN, totRE);

    // ---- pipelined scatter || spmm0, per rating ----
    for (int s = 0; s <= R; s++) {
        int rs = (s < R) ? s : -1;
        int rp = s - 1;
        int sb = (rs >= 0) ? scatBlocksPerR : 0;
        int pb = (rp >= 0) ? spmmBlocksPerR : 0;
        scatter_spmm0_kernel<<<sb + pb, 256>>>(
            rows, cols, vals, E, N, deg, edges, rs, sb,
            startp, bufA, bufB, sumb, need, rp, pb);
    }

    // ---- modes 1 and 2 over all ratings ----
    const int spmm_grid = (totRN + 31) / 32;
    spmm_all_kernel<<<spmm_grid, 256>>>(startp, edges, bufB, bufA, sumb, need,
                                        N, totRN, 1, 0ull);
    spmm_all_kernel<<<spmm_grid, 256>>>(startp, edges, bufA, bufB, sumb, need,
                                        N, totRN, 2, mask2);

    const float invR2 = 1.0f / (float)(R * R);
    const int fin_grid = (B + 7) / 8;
    final_kernel<<<fin_grid, 256>>>(users, items, sumb, U, invR2,
                                    (float*)d_out, B);
}